// round 10
// baseline (speedup 1.0000x reference)
#include <cuda_runtime.h>
#include <cuda_fp16.h>
#include <cstdint>
#include <cstddef>

// Problem constants
#define BB 512
#define TT 128
#define HH 1024
#define BH (512*1024)
#define NSTEPS 129

// ---------------- device scratch (no allocations allowed) ----------------
__device__ __align__(16) __half g_U1[1088 * 4096];  // [k][n] row-major, gate-interleaved n
__device__ __align__(16) __half g_U2[2048 * 4096];
__device__ __align__(16) float  g_bp1[4096];
__device__ __align__(16) float  g_bp2[4096];
__device__ __align__(16) __half g_xh[BB * TT * 64];
__device__ __align__(16) __half g_h1[2][BH];
__device__ __align__(16) __half g_h2[2][BH];
__device__ __align__(16) float  g_c1[BH];
__device__ __align__(16) float  g_c2[BH];
__device__ int g_tick[NSTEPS];          // per-launch tile tickets (zeroed each replay)

// ---------------- ptx helpers ----------------
__device__ __forceinline__ void cp16(uint32_t dst, const void* src) {
    asm volatile("cp.async.cg.shared.global [%0], [%1], 16;\n" :: "r"(dst), "l"(src));
}
__device__ __forceinline__ void cp_commit() { asm volatile("cp.async.commit_group;\n"); }
template<int N> __device__ __forceinline__ void cp_wait() {
    asm volatile("cp.async.wait_group %0;\n" :: "n"(N));
}
__device__ __forceinline__ void ldmA(uint32_t* r, uint32_t a) {
    asm volatile("ldmatrix.sync.aligned.m8n8.x4.shared.b16 {%0,%1,%2,%3}, [%4];\n"
        : "=r"(r[0]), "=r"(r[1]), "=r"(r[2]), "=r"(r[3]) : "r"(a));
}
__device__ __forceinline__ void ldmBT(uint32_t* r, uint32_t a) {
    asm volatile("ldmatrix.sync.aligned.m8n8.x4.trans.shared.b16 {%0,%1,%2,%3}, [%4];\n"
        : "=r"(r[0]), "=r"(r[1]), "=r"(r[2]), "=r"(r[3]) : "r"(a));
}
__device__ __forceinline__ void mma_f16(float c[4], const uint32_t a[4], uint32_t b0, uint32_t b1) {
    asm volatile("mma.sync.aligned.m16n8k16.row.col.f32.f16.f16.f32 "
        "{%0,%1,%2,%3}, {%4,%5,%6,%7}, {%8,%9}, {%0,%1,%2,%3};\n"
        : "+f"(c[0]), "+f"(c[1]), "+f"(c[2]), "+f"(c[3])
        : "r"(a[0]), "r"(a[1]), "r"(a[2]), "r"(a[3]), "r"(b0), "r"(b1));
}
__device__ __forceinline__ float tanh_ap(float x) {
    float y; asm("tanh.approx.f32 %0, %1;" : "=f"(y) : "f"(x)); return y;
}
__device__ __forceinline__ float sigm_t(float x) {   // sigmoid via 1 MUFU
    return fmaf(tanh_ap(0.5f * x), 0.5f, 0.5f);
}

// ---------------- pack / prep kernels (run each replay; cheap) ----------------
__global__ void pack_u1(const float* __restrict__ W1, const float* __restrict__ U1) {
    int idx = blockIdx.x * 256 + threadIdx.x;
    if (idx >= 1088 * 4096) return;
    int k = idx >> 12, np = idx & 4095;
    int j = np >> 2, g = np & 3;
    int n = g * 1024 + j;
    float v = (k < 64) ? W1[(size_t)k * 4096 + n] : U1[(size_t)(k - 64) * 4096 + n];
    g_U1[idx] = __float2half(v);
}
__global__ void pack_u2(const float* __restrict__ W2, const float* __restrict__ U2) {
    int idx = blockIdx.x * 256 + threadIdx.x;
    if (idx >= 2048 * 4096) return;
    int k = idx >> 12, np = idx & 4095;
    int j = np >> 2, g = np & 3;
    int n = g * 1024 + j;
    float v = (k < 1024) ? W2[(size_t)k * 4096 + n] : U2[(size_t)(k - 1024) * 4096 + n];
    g_U2[idx] = __float2half(v);
}
__global__ void prep_misc(const float* __restrict__ x,
                          const float* __restrict__ b1, const float* __restrict__ b2) {
    int i = blockIdx.x * 256 + threadIdx.x;
    if (i < BB * TT * 64) g_xh[i] = __float2half(x[i]);
    if (i < BH) {
        g_c1[i] = 0.f; g_c2[i] = 0.f;
        __half z = __float2half(0.f);
        g_h1[0][i] = z; g_h1[1][i] = z; g_h2[0][i] = z; g_h2[1][i] = z;
    }
    if (i < 4096) {
        int j = i >> 2, g = i & 3;
        g_bp1[i] = b1[g * 1024 + j];
        g_bp2[i] = b2[g * 1024 + j];
    }
    if (i < NSTEPS) g_tick[i] = 0;
}

// ---------------- dynamically balanced paired LSTM step ----------------
// One launch per wavefront step s: layer0@t=s (light, 17 chunk-units) and
// layer1@t=s-1 (heavy, 32 units). 296 CTAs pull tiles from a per-launch atomic
// ticket, heavy tiles first (LPT) -> makespan ~= ideal + tail instead of the
// static worst-SM 49u. Launch boundaries provide all ordering (no fences/spins).
// CTA tile 128x128, 8 warps of 32x64, K-chunk 64, 3-stage cp.async pipeline.
#define A_PITCH 72              // halves (64 + 8 pad)
#define B_PITCH 136             // halves (128 + 8 pad)
#define STAGE_A (128 * A_PITCH * 2)     // 18432
#define STAGE_B (64 * B_PITCH * 2)      // 17408
#define STAGE   (STAGE_A + STAGE_B)     // 35840
#define SMEM_TOTAL (3 * STAGE)          // 107520

__global__ __launch_bounds__(256, 2) void lstm_pair(int s) {
    extern __shared__ __align__(16) char smem[];
    __shared__ int s_item;
    const int tid = threadIdx.x;
    const int wid = tid >> 5, lane = tid & 31;
    const uint32_t sSm = (uint32_t)__cvta_generic_to_shared(smem);
    const int wm = (wid >> 1) * 32;     // 4 m-warps x 32 rows
    const int wn = (wid & 1) * 64;      // 2 n-warps x 64 cols

    const int nH = (s >= 1) ? 128 : 0;          // heavy items first (LPT)
    const int nL = (s <= 127) ? 128 : 0;
    const int nItems = nH + nL;

    for (;;) {
        if (tid == 0) s_item = atomicAdd(&g_tick[s], 1);
        __syncthreads();
        const int k = s_item;
        if (k >= nItems) break;
        const int layer = (k < nH) ? 1 : 0;
        const int tile = (k < nH) ? k : (k - nH);
        const int t = layer ? s - 1 : s;

        const int mblk = (tile >> 5) << 7;
        const int nblk = (tile & 31) << 7;
        const int cur = t & 1, prev = cur ^ 1;
        const __half *A0, *A1, *Bw; const float* biasp; float* cst; __half* hout;
        int lda0, K0, KTOT;
        if (layer == 0) {
            A0 = g_xh + t * 64; lda0 = TT * 64; K0 = 64;
            A1 = g_h1[prev]; Bw = g_U1; biasp = g_bp1; cst = g_c1; hout = g_h1[cur]; KTOT = 1088;
        } else {
            A0 = g_h1[cur]; lda0 = 1024; K0 = 1024;
            A1 = g_h2[prev]; Bw = g_U2; biasp = g_bp2; cst = g_c2; hout = g_h2[cur]; KTOT = 2048;
        }
        const int KT = KTOT >> 6;

        float acc[2][8][4];
#pragma unroll
        for (int a = 0; a < 2; a++)
#pragma unroll
            for (int b = 0; b < 8; b++)
#pragma unroll
                for (int c = 0; c < 4; c++) acc[a][b][c] = 0.f;

        auto issue = [&](int kt) {
            const int st = kt % 3;
            const int kg = kt << 6;
            const __half* srcA; int lda, kr;
            if (kg < K0) { srcA = A0; lda = lda0; kr = kg; }
            else         { srcA = A1; lda = 1024; kr = kg - K0; }
            const uint32_t aBase = sSm + st * STAGE;
#pragma unroll
            for (int jj = 0; jj < 4; jj++) {
                int item = jj * 256 + tid;
                int row = item >> 3, c8 = item & 7;
                cp16(aBase + (uint32_t)(row * (A_PITCH * 2) + c8 * 16),
                     srcA + (size_t)(mblk + row) * lda + kr + c8 * 8);
            }
            const uint32_t bBase = aBase + STAGE_A;
#pragma unroll
            for (int jj = 0; jj < 4; jj++) {
                int item = jj * 256 + tid;
                int row = item >> 4, c16 = item & 15;
                cp16(bBase + (uint32_t)(row * (B_PITCH * 2) + c16 * 16),
                     Bw + (size_t)(kg + row) * 4096 + nblk + c16 * 8);
            }
            cp_commit();
        };

        const uint32_t aLane = (uint32_t)(((wm + (lane & 15)) * A_PITCH + ((lane >> 4) << 3)) * 2);
        const uint32_t bLane = (uint32_t)(((lane & 15) * B_PITCH + wn + ((lane >> 4) << 3)) * 2);

        uint32_t af[2][2][4], bf[2][4][4];
        auto load_frags = [&](uint32_t aB, uint32_t bB, int kk, int buf) {
#pragma unroll
            for (int mi = 0; mi < 2; mi++)
                ldmA(af[buf][mi], aB + aLane + (uint32_t)((mi * 16 * A_PITCH + kk * 16) * 2));
#pragma unroll
            for (int nj = 0; nj < 4; nj++)
                ldmBT(bf[buf][nj], bB + bLane + (uint32_t)((kk * 16 * B_PITCH + nj * 16) * 2));
        };
        auto do_mma = [&](int buf) {
#pragma unroll
            for (int mi = 0; mi < 2; mi++)
#pragma unroll
                for (int ni = 0; ni < 8; ni++)
                    mma_f16(acc[mi][ni], af[buf][mi],
                            bf[buf][ni >> 1][(ni & 1) * 2], bf[buf][ni >> 1][(ni & 1) * 2 + 1]);
        };

        // prologue: fill stages 0,1; publish stage 0; preload kk0 frags; fill stage 2
        issue(0); issue(1);
        cp_wait<1>();
        __syncthreads();
        load_frags(sSm, sSm + STAGE_A, 0, 0);
        issue(2);

        for (int kt = 0; kt < KT; kt++) {
            const uint32_t aB = sSm + (kt % 3) * STAGE;
            const uint32_t bB = aB + STAGE_A;
#pragma unroll
            for (int kk = 0; kk < 3; kk++) {
                load_frags(aB, bB, kk + 1, (kk & 1) ^ 1);
                do_mma(kk & 1);
            }
            if (kt + 1 < KT) cp_wait<1>(); else cp_wait<0>();
            __syncthreads();
            if (kt + 1 < KT) {
                const uint32_t aB2 = sSm + ((kt + 1) % 3) * STAGE;
                load_frags(aB2, aB2 + STAGE_A, 0, 0);
            }
            if (kt + 3 < KT) issue(kt + 3);
            do_mma(1);
        }

        // epilogue: smem patch -> gates -> c,h (coalesced, MUFU-light)
        __syncthreads();
        float* patch = (float*)smem;
#pragma unroll
        for (int mi = 0; mi < 2; mi++)
#pragma unroll
            for (int ni = 0; ni < 8; ni++) {
                int rr = wm + mi * 16 + (lane >> 2);
                int cc = wn + ni * 8 + (lane & 3) * 2;
                *(float2*)(patch + rr * B_PITCH + cc)       = make_float2(acc[mi][ni][0], acc[mi][ni][1]);
                *(float2*)(patch + (rr + 8) * B_PITCH + cc) = make_float2(acc[mi][ni][2], acc[mi][ni][3]);
            }
        __syncthreads();

        const int jbase = nblk >> 2;
#pragma unroll 4
        for (int it = 0; it < 16; it++) {
            int idx2 = it * 256 + tid;
            int row = idx2 >> 5;
            int u = idx2 & 31;
            float4 z = *(float4*)(patch + row * B_PITCH + u * 4);
            float4 bb = *(const float4*)(biasp + ((jbase + u) << 2));
            float ig = sigm_t(z.x + bb.x);
            float fg = sigm_t(z.y + bb.y);
            float gg = tanh_ap(z.z + bb.z);
            float og = sigm_t(z.w + bb.w);
            size_t off = (size_t)(mblk + row) * 1024 + jbase + u;
            float cn = fg * cst[off] + ig * gg;
            cst[off] = cn;
            hout[off] = __float2half(og * tanh_ap(cn));
        }
        __syncthreads();   // all threads done with smem before next ticket reuses it
    }
}

// ---------------- dense sigmoid head ----------------
__global__ void head_kernel(const float* __restrict__ Wd, const float* __restrict__ bd,
                            float* __restrict__ out) {
    int b = blockIdx.x;
    const __half* h = g_h2[1] + (size_t)b * 1024;   // t=127 -> cur buffer = 1
    float s = 0.f;
    for (int j = threadIdx.x; j < 1024; j += 128)
        s += __half2float(h[j]) * Wd[j];
#pragma unroll
    for (int o = 16; o; o >>= 1) s += __shfl_xor_sync(0xffffffffu, s, o);
    __shared__ float ws[4];
    if ((threadIdx.x & 31) == 0) ws[threadIdx.x >> 5] = s;
    __syncthreads();
    if (threadIdx.x == 0) {
        float t = ws[0] + ws[1] + ws[2] + ws[3] + bd[0];
        out[b] = 1.f / (1.f + __expf(-t));
    }
}

// ---------------- launch ----------------
extern "C" void kernel_launch(void* const* d_in, const int* in_sizes, int n_in,
                              void* d_out, int out_size) {
    (void)in_sizes; (void)n_in; (void)out_size;
    const float* x  = (const float*)d_in[0];
    const float* W1 = (const float*)d_in[1];
    const float* U1 = (const float*)d_in[2];
    const float* b1 = (const float*)d_in[3];
    const float* W2 = (const float*)d_in[4];
    const float* U2 = (const float*)d_in[5];
    const float* b2 = (const float*)d_in[6];
    const float* Wd = (const float*)d_in[7];
    const float* bd = (const float*)d_in[8];
    float* out = (float*)d_out;

    cudaFuncSetAttribute(lstm_pair, cudaFuncAttributeMaxDynamicSharedMemorySize, SMEM_TOTAL);

    pack_u1<<<(1088 * 4096 + 255) / 256, 256>>>(W1, U1);       // 1
    pack_u2<<<(2048 * 4096 + 255) / 256, 256>>>(W2, U2);       // 2
    prep_misc<<<(BB * TT * 64 + 255) / 256, 256>>>(x, b1, b2); // 3

    for (int s = 0; s < NSTEPS; s++) {                         // 4 = first lstm (ncu slot)
        lstm_pair<<<296, 256, SMEM_TOTAL>>>(s);
    }
    head_kernel<<<512, 128>>>(Wd, bd, out);
}

// round 11
// speedup vs baseline: 1.2346x; 1.2346x over previous
#include <cuda_runtime.h>
#include <cuda_fp16.h>
#include <cstdint>
#include <cstddef>

// Problem constants
#define BB 512
#define TT 128
#define HH 1024
#define BH (512*1024)

// ---------------- device scratch (no allocations allowed) ----------------
__device__ __align__(16) __half g_U1[1088 * 4096];  // [k][n] row-major, gate-interleaved n
__device__ __align__(16) __half g_U2[2048 * 4096];
__device__ __align__(16) float  g_bp1[4096];
__device__ __align__(16) float  g_bp2[4096];
__device__ __align__(16) __half g_xh[BB * TT * 64];
__device__ __align__(16) __half g_h1[2][BH];
__device__ __align__(16) __half g_h2[2][BH];
__device__ __align__(16) float  g_c1[BH];
__device__ __align__(16) float  g_c2[BH];

// ---------------- ptx helpers ----------------
__device__ __forceinline__ void cp16(uint32_t dst, const void* src) {
    asm volatile("cp.async.cg.shared.global [%0], [%1], 16;\n" :: "r"(dst), "l"(src));
}
__device__ __forceinline__ void cp_commit() { asm volatile("cp.async.commit_group;\n"); }
template<int N> __device__ __forceinline__ void cp_wait() {
    asm volatile("cp.async.wait_group %0;\n" :: "n"(N));
}
__device__ __forceinline__ void ldmA(uint32_t* r, uint32_t a) {
    asm volatile("ldmatrix.sync.aligned.m8n8.x4.shared.b16 {%0,%1,%2,%3}, [%4];\n"
        : "=r"(r[0]), "=r"(r[1]), "=r"(r[2]), "=r"(r[3]) : "r"(a));
}
__device__ __forceinline__ void ldmBT(uint32_t* r, uint32_t a) {
    asm volatile("ldmatrix.sync.aligned.m8n8.x4.trans.shared.b16 {%0,%1,%2,%3}, [%4];\n"
        : "=r"(r[0]), "=r"(r[1]), "=r"(r[2]), "=r"(r[3]) : "r"(a));
}
__device__ __forceinline__ void mma_f16(float c[4], const uint32_t a[4], uint32_t b0, uint32_t b1) {
    asm volatile("mma.sync.aligned.m16n8k16.row.col.f32.f16.f16.f32 "
        "{%0,%1,%2,%3}, {%4,%5,%6,%7}, {%8,%9}, {%0,%1,%2,%3};\n"
        : "+f"(c[0]), "+f"(c[1]), "+f"(c[2]), "+f"(c[3])
        : "r"(a[0]), "r"(a[1]), "r"(a[2]), "r"(a[3]), "r"(b0), "r"(b1));
}
__device__ __forceinline__ float tanh_ap(float x) {
    float y; asm("tanh.approx.f32 %0, %1;" : "=f"(y) : "f"(x)); return y;
}
__device__ __forceinline__ float sigm_t(float x) {   // sigmoid via 1 MUFU
    return fmaf(tanh_ap(0.5f * x), 0.5f, 0.5f);
}

// ---------------- pack / prep kernels (run each replay; cheap) ----------------
__global__ void pack_u1(const float* __restrict__ W1, const float* __restrict__ U1) {
    int idx = blockIdx.x * 256 + threadIdx.x;
    if (idx >= 1088 * 4096) return;
    int k = idx >> 12, np = idx & 4095;
    int j = np >> 2, g = np & 3;
    int n = g * 1024 + j;
    float v = (k < 64) ? W1[(size_t)k * 4096 + n] : U1[(size_t)(k - 64) * 4096 + n];
    g_U1[idx] = __float2half(v);
}
__global__ void pack_u2(const float* __restrict__ W2, const float* __restrict__ U2) {
    int idx = blockIdx.x * 256 + threadIdx.x;
    if (idx >= 2048 * 4096) return;
    int k = idx >> 12, np = idx & 4095;
    int j = np >> 2, g = np & 3;
    int n = g * 1024 + j;
    float v = (k < 1024) ? W2[(size_t)k * 4096 + n] : U2[(size_t)(k - 1024) * 4096 + n];
    g_U2[idx] = __float2half(v);
}
__global__ void prep_misc(const float* __restrict__ x,
                          const float* __restrict__ b1, const float* __restrict__ b2) {
    int i = blockIdx.x * 256 + threadIdx.x;
    if (i < BB * TT * 64) g_xh[i] = __float2half(x[i]);
    if (i < BH) {
        g_c1[i] = 0.f; g_c2[i] = 0.f;
        __half z = __float2half(0.f);
        g_h1[0][i] = z; g_h1[1][i] = z; g_h2[0][i] = z; g_h2[1][i] = z;
    }
    if (i < 4096) {
        int j = i >> 2, g = i & 3;
        g_bp1[i] = b1[g * 1024 + j];
        g_bp2[i] = b2[g * 1024 + j];
    }
}

// ---------------- paired fused LSTM step (R8 static mapping, templated body) ----
// bids 0-127 -> HEAVY layer1 tiles (K=2048); bids 128-255 -> LIGHT layer0 (K=1088).
// Classic bid->SM map gives every 2-CTA SM one heavy + one light (49u critical).
// CTA tile 128x128, 8 warps of 32x64, K-chunk 64, 3-stage cp.async, chunk-level
// software pipeline with dual fragment buffers. LAYER template folds K0/KT/LDA
// into constants. 2 CTAs/SM.
#define A_PITCH 72              // halves (64 + 8 pad)
#define B_PITCH 136             // halves (128 + 8 pad)
#define STAGE_A (128 * A_PITCH * 2)     // 18432
#define STAGE_B (64 * B_PITCH * 2)      // 17408
#define STAGE   (STAGE_A + STAGE_B)     // 35840
#define SMEM_TOTAL (3 * STAGE)          // 107520

template<int LAYER>
__device__ __forceinline__ void run_tile(int t, int tile, char* smem) {
    constexpr int K0   = LAYER ? 1024 : 64;
    constexpr int KTOT = LAYER ? 2048 : 1088;
    constexpr int KT   = KTOT >> 6;
    constexpr int LDA0 = LAYER ? 1024 : (TT * 64);

    const int tid = threadIdx.x;
    const int wid = tid >> 5, lane = tid & 31;
    const uint32_t sSm = (uint32_t)__cvta_generic_to_shared(smem);
    const int wm = (wid >> 1) * 32;     // 4 m-warps x 32 rows
    const int wn = (wid & 1) * 64;      // 2 n-warps x 64 cols

    const int mblk = (tile >> 5) << 7;
    const int nblk = (tile & 31) << 7;
    const int cur = t & 1, prev = cur ^ 1;

    const __half* A0   = LAYER ? g_h1[cur]  : (g_xh + t * 64);
    const __half* A1   = LAYER ? g_h2[prev] : g_h1[prev];
    const __half* Bw   = LAYER ? g_U2  : g_U1;
    const float* biasp = LAYER ? g_bp2 : g_bp1;
    float*       cst   = LAYER ? g_c2  : g_c1;
    __half*      hout  = LAYER ? g_h2[cur] : g_h1[cur];

    float acc[2][8][4];
#pragma unroll
    for (int a = 0; a < 2; a++)
#pragma unroll
        for (int b = 0; b < 8; b++)
#pragma unroll
            for (int c = 0; c < 4; c++) acc[a][b][c] = 0.f;

    auto issue = [&](int kt) {
        const int st = kt % 3;
        const int kg = kt << 6;
        const __half* srcA; int lda, kr;
        if (kg < K0) { srcA = A0; lda = LDA0; kr = kg; }
        else         { srcA = A1; lda = 1024; kr = kg - K0; }
        const uint32_t aBase = sSm + st * STAGE;
#pragma unroll
        for (int jj = 0; jj < 4; jj++) {
            int item = jj * 256 + tid;
            int row = item >> 3, c8 = item & 7;
            cp16(aBase + (uint32_t)(row * (A_PITCH * 2) + c8 * 16),
                 srcA + (size_t)(mblk + row) * lda + kr + c8 * 8);
        }
        const uint32_t bBase = aBase + STAGE_A;
#pragma unroll
        for (int jj = 0; jj < 4; jj++) {
            int item = jj * 256 + tid;
            int row = item >> 4, c16 = item & 15;
            cp16(bBase + (uint32_t)(row * (B_PITCH * 2) + c16 * 16),
                 Bw + (size_t)(kg + row) * 4096 + nblk + c16 * 8);
        }
        cp_commit();
    };

    const uint32_t aLane = (uint32_t)(((wm + (lane & 15)) * A_PITCH + ((lane >> 4) << 3)) * 2);
    const uint32_t bLane = (uint32_t)(((lane & 15) * B_PITCH + wn + ((lane >> 4) << 3)) * 2);

    uint32_t af[2][2][4], bf[2][4][4];
    auto load_frags = [&](uint32_t aB, uint32_t bB, int kk, int buf) {
#pragma unroll
        for (int mi = 0; mi < 2; mi++)
            ldmA(af[buf][mi], aB + aLane + (uint32_t)((mi * 16 * A_PITCH + kk * 16) * 2));
#pragma unroll
        for (int nj = 0; nj < 4; nj++)
            ldmBT(bf[buf][nj], bB + bLane + (uint32_t)((kk * 16 * B_PITCH + nj * 16) * 2));
    };
    auto do_mma = [&](int buf) {
#pragma unroll
        for (int mi = 0; mi < 2; mi++)
#pragma unroll
            for (int ni = 0; ni < 8; ni++)
                mma_f16(acc[mi][ni], af[buf][mi],
                        bf[buf][ni >> 1][(ni & 1) * 2], bf[buf][ni >> 1][(ni & 1) * 2 + 1]);
    };

    // prologue: fill stages 0,1; publish stage 0; preload kk0 frags; fill stage 2
    issue(0); issue(1);
    cp_wait<1>();
    __syncthreads();
    load_frags(sSm, sSm + STAGE_A, 0, 0);
    issue(2);

#pragma unroll 1
    for (int kt = 0; kt < KT; kt++) {
        const uint32_t aB = sSm + (kt % 3) * STAGE;
        const uint32_t bB = aB + STAGE_A;
#pragma unroll
        for (int kk = 0; kk < 3; kk++) {
            load_frags(aB, bB, kk + 1, (kk & 1) ^ 1);
            do_mma(kk & 1);
        }
        if (kt + 1 < KT) cp_wait<1>(); else cp_wait<0>();
        __syncthreads();
        if (kt + 1 < KT) {
            const uint32_t aB2 = sSm + ((kt + 1) % 3) * STAGE;
            load_frags(aB2, aB2 + STAGE_A, 0, 0);
        }
        if (kt + 3 < KT) issue(kt + 3);
        do_mma(1);
    }

    // epilogue: smem patch -> gates -> c,h (coalesced, MUFU-light)
    __syncthreads();
    float* patch = (float*)smem;
#pragma unroll
    for (int mi = 0; mi < 2; mi++)
#pragma unroll
        for (int ni = 0; ni < 8; ni++) {
            int rr = wm + mi * 16 + (lane >> 2);
            int cc = wn + ni * 8 + (lane & 3) * 2;
            *(float2*)(patch + rr * B_PITCH + cc)       = make_float2(acc[mi][ni][0], acc[mi][ni][1]);
            *(float2*)(patch + (rr + 8) * B_PITCH + cc) = make_float2(acc[mi][ni][2], acc[mi][ni][3]);
        }
    __syncthreads();

    const int jbase = nblk >> 2;
#pragma unroll 4
    for (int it = 0; it < 16; it++) {
        int idx2 = it * 256 + tid;
        int row = idx2 >> 5;
        int u = idx2 & 31;
        float4 z = *(float4*)(patch + row * B_PITCH + u * 4);
        float4 bb = *(const float4*)(biasp + ((jbase + u) << 2));
        float ig = sigm_t(z.x + bb.x);
        float fg = sigm_t(z.y + bb.y);
        float gg = tanh_ap(z.z + bb.z);
        float og = sigm_t(z.w + bb.w);
        size_t off = (size_t)(mblk + row) * 1024 + jbase + u;
        float cn = fg * cst[off] + ig * gg;
        cst[off] = cn;
        hout[off] = __float2half(og * tanh_ap(cn));
    }
}

__global__ __launch_bounds__(256, 2) void lstm_pair(int t0, int t1) {
    extern __shared__ __align__(16) char smem[];
    const int bid = blockIdx.x;
    const int layer = (bid < 128) ? 1 : 0;        // heavy tiles on low bids
    const int tile = bid & 127;
    const int t = layer ? t1 : t0;
    if (t < 0 || t > 127) return;
    if (layer) run_tile<1>(t, tile, smem);
    else       run_tile<0>(t, tile, smem);
}

// ---------------- dense sigmoid head ----------------
__global__ void head_kernel(const float* __restrict__ Wd, const float* __restrict__ bd,
                            float* __restrict__ out) {
    int b = blockIdx.x;
    const __half* h = g_h2[1] + (size_t)b * 1024;   // t=127 -> cur buffer = 1
    float s = 0.f;
    for (int j = threadIdx.x; j < 1024; j += 128)
        s += __half2float(h[j]) * Wd[j];
#pragma unroll
    for (int o = 16; o; o >>= 1) s += __shfl_xor_sync(0xffffffffu, s, o);
    __shared__ float ws[4];
    if ((threadIdx.x & 31) == 0) ws[threadIdx.x >> 5] = s;
    __syncthreads();
    if (threadIdx.x == 0) {
        float t = ws[0] + ws[1] + ws[2] + ws[3] + bd[0];
        out[b] = 1.f / (1.f + __expf(-t));
    }
}

// ---------------- launch ----------------
extern "C" void kernel_launch(void* const* d_in, const int* in_sizes, int n_in,
                              void* d_out, int out_size) {
    (void)in_sizes; (void)n_in; (void)out_size;
    const float* x  = (const float*)d_in[0];
    const float* W1 = (const float*)d_in[1];
    const float* U1 = (const float*)d_in[2];
    const float* b1 = (const float*)d_in[3];
    const float* W2 = (const float*)d_in[4];
    const float* U2 = (const float*)d_in[5];
    const float* b2 = (const float*)d_in[6];
    const float* Wd = (const float*)d_in[7];
    const float* bd = (const float*)d_in[8];
    float* out = (float*)d_out;

    cudaFuncSetAttribute(lstm_pair, cudaFuncAttributeMaxDynamicSharedMemorySize, SMEM_TOTAL);

    pack_u1<<<(1088 * 4096 + 255) / 256, 256>>>(W1, U1);       // 1
    pack_u2<<<(2048 * 4096 + 255) / 256, 256>>>(W2, U2);       // 2
    prep_misc<<<(BB * TT * 64 + 255) / 256, 256>>>(x, b1, b2); // 3

    // wavefront: layer0@t0 (light, bids 128-255) + layer1@t0-1 (heavy, bids 0-127)
    for (int t0 = 0; t0 < 128; t0++) {
        lstm_pair<<<256, 256, SMEM_TOTAL>>>(t0, t0 - 1);
    }
    lstm_pair<<<128, 256, SMEM_TOTAL>>>(128, 127);   // final: heavy-only, exact grid
    head_kernel<<<512, 128>>>(Wd, bd, out);
}

// round 12
// speedup vs baseline: 1.3040x; 1.0562x over previous
#include <cuda_runtime.h>
#include <cuda_fp16.h>
#include <cstdint>
#include <cstddef>

// Problem constants
#define BB 512
#define TT 128
#define HH 1024
#define BH (512*1024)

// ---------------- device scratch (no allocations allowed) ----------------
__device__ __align__(16) __half g_U1[1088 * 4096];  // [k][n] row-major, gate-interleaved n
__device__ __align__(16) __half g_U2[2048 * 4096];
__device__ __align__(16) float  g_bp1[4096];
__device__ __align__(16) float  g_bp2[4096];
__device__ __align__(16) __half g_xh[BB * TT * 64];
__device__ __align__(16) __half g_h1[2][BH];
__device__ __align__(16) __half g_h2[2][BH];
__device__ __align__(16) float  g_c1[BH];
__device__ __align__(16) float  g_c2[BH];

// ---------------- ptx helpers ----------------
__device__ __forceinline__ void cp16(uint32_t dst, const void* src) {
    asm volatile("cp.async.cg.shared.global [%0], [%1], 16;\n" :: "r"(dst), "l"(src));
}
__device__ __forceinline__ void cp_commit() { asm volatile("cp.async.commit_group;\n"); }
template<int N> __device__ __forceinline__ void cp_wait() {
    asm volatile("cp.async.wait_group %0;\n" :: "n"(N));
}
__device__ __forceinline__ void ldmA(uint32_t* r, uint32_t a) {
    asm volatile("ldmatrix.sync.aligned.m8n8.x4.shared.b16 {%0,%1,%2,%3}, [%4];\n"
        : "=r"(r[0]), "=r"(r[1]), "=r"(r[2]), "=r"(r[3]) : "r"(a));
}
__device__ __forceinline__ void ldmBT(uint32_t* r, uint32_t a) {
    asm volatile("ldmatrix.sync.aligned.m8n8.x4.trans.shared.b16 {%0,%1,%2,%3}, [%4];\n"
        : "=r"(r[0]), "=r"(r[1]), "=r"(r[2]), "=r"(r[3]) : "r"(a));
}
__device__ __forceinline__ void mma_f16(float c[4], const uint32_t a[4], uint32_t b0, uint32_t b1) {
    asm volatile("mma.sync.aligned.m16n8k16.row.col.f32.f16.f16.f32 "
        "{%0,%1,%2,%3}, {%4,%5,%6,%7}, {%8,%9}, {%0,%1,%2,%3};\n"
        : "+f"(c[0]), "+f"(c[1]), "+f"(c[2]), "+f"(c[3])
        : "r"(a[0]), "r"(a[1]), "r"(a[2]), "r"(a[3]), "r"(b0), "r"(b1));
}
__device__ __forceinline__ float tanh_ap(float x) {
    float y; asm("tanh.approx.f32 %0, %1;" : "=f"(y) : "f"(x)); return y;
}
__device__ __forceinline__ float sigm_t(float x) {   // sigmoid via 1 MUFU
    return fmaf(tanh_ap(0.5f * x), 0.5f, 0.5f);
}

// ---------------- pack / prep kernels (run each replay) ----------------
// Fully-coalesced gate-interleave pack: thread (k,j) reads src[k][g*1024+j]
// (coalesced across j for each g) and writes halfs [g0,g1,g2,g3] at out[k][4j]
// as one 8B store (coalesced). Same __float2half rounding as before.
__global__ void pack_u1(const float* __restrict__ W1, const float* __restrict__ U1) {
    int idx = blockIdx.x * 256 + threadIdx.x;      // 1088*1024 threads
    if (idx >= 1088 * 1024) return;
    int j = idx & 1023, k = idx >> 10;
    const float* src = (k < 64) ? (W1 + (size_t)k * 4096)
                                : (U1 + (size_t)(k - 64) * 4096);
    union { __half h[4]; uint2 u; } o;
    o.h[0] = __float2half(src[j]);
    o.h[1] = __float2half(src[1024 + j]);
    o.h[2] = __float2half(src[2048 + j]);
    o.h[3] = __float2half(src[3072 + j]);
    *(uint2*)(g_U1 + (size_t)k * 4096 + 4 * j) = o.u;
}
__global__ void pack_u2(const float* __restrict__ W2, const float* __restrict__ U2) {
    int idx = blockIdx.x * 256 + threadIdx.x;      // 2048*1024 threads
    if (idx >= 2048 * 1024) return;
    int j = idx & 1023, k = idx >> 10;
    const float* src = (k < 1024) ? (W2 + (size_t)k * 4096)
                                  : (U2 + (size_t)(k - 1024) * 4096);
    union { __half h[4]; uint2 u; } o;
    o.h[0] = __float2half(src[j]);
    o.h[1] = __float2half(src[1024 + j]);
    o.h[2] = __float2half(src[2048 + j]);
    o.h[3] = __float2half(src[3072 + j]);
    *(uint2*)(g_U2 + (size_t)k * 4096 + 4 * j) = o.u;
}
__global__ void prep_misc(const float* __restrict__ x,
                          const float* __restrict__ b1, const float* __restrict__ b2) {
    int i = blockIdx.x * 256 + threadIdx.x;
    if (i < BB * TT * 64) g_xh[i] = __float2half(x[i]);
    if (i < BH) {
        g_c1[i] = 0.f; g_c2[i] = 0.f;
        __half z = __float2half(0.f);
        g_h1[0][i] = z; g_h1[1][i] = z; g_h2[0][i] = z; g_h2[1][i] = z;
    }
    if (i < 4096) {
        int j = i >> 2, g = i & 3;
        g_bp1[i] = b1[g * 1024 + j];
        g_bp2[i] = b2[g * 1024 + j];
    }
}

// ---------------- paired fused LSTM step (exact R8 body) ----------------
// bids 0-127 -> HEAVY layer1 tiles (K=2048); bids 128-255 -> LIGHT layer0 (K=1088).
// Classic bid->SM map pairs one heavy + one light per 2-CTA SM (49u critical path).
// CTA tile 128x128, 8 warps of 32x64, K-chunk 64, 3-stage cp.async, chunk-level
// software pipeline with dual fragment buffers. 2 CTAs/SM. Single body (I$-safe).
#define A_PITCH 72              // halves (64 + 8 pad)
#define B_PITCH 136             // halves (128 + 8 pad)
#define STAGE_A (128 * A_PITCH * 2)     // 18432
#define STAGE_B (64 * B_PITCH * 2)      // 17408
#define STAGE   (STAGE_A + STAGE_B)     // 35840
#define SMEM_TOTAL (3 * STAGE)          // 107520

__global__ __launch_bounds__(256, 2) void lstm_pair(int t0, int t1) {
    const int bid = blockIdx.x;
    const int layer = (bid < 128) ? 1 : 0;        // heavy tiles on low bids
    const int tile = bid & 127;
    const int t = layer ? t1 : t0;
    if (t < 0 || t > 127) return;

    extern __shared__ __align__(16) char smem[];
    const int tid = threadIdx.x;
    const int wid = tid >> 5, lane = tid & 31;
    const int mblk = (tile >> 5) << 7;
    const int nblk = (tile & 31) << 7;

    const int cur = t & 1, prev = cur ^ 1;
    const __half *A0, *A1, *Bw; const float* biasp; float* cst; __half* hout;
    int lda0, K0, KTOT;
    if (layer == 0) {
        A0 = g_xh + t * 64; lda0 = TT * 64; K0 = 64;
        A1 = g_h1[prev]; Bw = g_U1; biasp = g_bp1; cst = g_c1; hout = g_h1[cur]; KTOT = 1088;
    } else {
        A0 = g_h1[cur]; lda0 = 1024; K0 = 1024;
        A1 = g_h2[prev]; Bw = g_U2; biasp = g_bp2; cst = g_c2; hout = g_h2[cur]; KTOT = 2048;
    }
    const int KT = KTOT >> 6;

    const uint32_t sSm = (uint32_t)__cvta_generic_to_shared(smem);
    const int wm = (wid >> 1) * 32;     // 4 m-warps x 32 rows
    const int wn = (wid & 1) * 64;      // 2 n-warps x 64 cols

    float acc[2][8][4];
#pragma unroll
    for (int a = 0; a < 2; a++)
#pragma unroll
        for (int b = 0; b < 8; b++)
#pragma unroll
            for (int c = 0; c < 4; c++) acc[a][b][c] = 0.f;

    auto issue = [&](int kt) {
        const int st = kt % 3;
        const int kg = kt << 6;
        const __half* srcA; int lda, kr;
        if (kg < K0) { srcA = A0; lda = lda0; kr = kg; }
        else         { srcA = A1; lda = 1024; kr = kg - K0; }
        const uint32_t aBase = sSm + st * STAGE;
#pragma unroll
        for (int jj = 0; jj < 4; jj++) {
            int item = jj * 256 + tid;
            int row = item >> 3, c8 = item & 7;
            cp16(aBase + (uint32_t)(row * (A_PITCH * 2) + c8 * 16),
                 srcA + (size_t)(mblk + row) * lda + kr + c8 * 8);
        }
        const uint32_t bBase = aBase + STAGE_A;
#pragma unroll
        for (int jj = 0; jj < 4; jj++) {
            int item = jj * 256 + tid;
            int row = item >> 4, c16 = item & 15;
            cp16(bBase + (uint32_t)(row * (B_PITCH * 2) + c16 * 16),
                 Bw + (size_t)(kg + row) * 4096 + nblk + c16 * 8);
        }
        cp_commit();
    };

    const uint32_t aLane = (uint32_t)(((wm + (lane & 15)) * A_PITCH + ((lane >> 4) << 3)) * 2);
    const uint32_t bLane = (uint32_t)(((lane & 15) * B_PITCH + wn + ((lane >> 4) << 3)) * 2);

    uint32_t af[2][2][4], bf[2][4][4];
    auto load_frags = [&](uint32_t aB, uint32_t bB, int kk, int buf) {
#pragma unroll
        for (int mi = 0; mi < 2; mi++)
            ldmA(af[buf][mi], aB + aLane + (uint32_t)((mi * 16 * A_PITCH + kk * 16) * 2));
#pragma unroll
        for (int nj = 0; nj < 4; nj++)
            ldmBT(bf[buf][nj], bB + bLane + (uint32_t)((kk * 16 * B_PITCH + nj * 16) * 2));
    };
    auto do_mma = [&](int buf) {
#pragma unroll
        for (int mi = 0; mi < 2; mi++)
#pragma unroll
            for (int ni = 0; ni < 8; ni++)
                mma_f16(acc[mi][ni], af[buf][mi],
                        bf[buf][ni >> 1][(ni & 1) * 2], bf[buf][ni >> 1][(ni & 1) * 2 + 1]);
    };

    // prologue: fill stages 0,1; publish stage 0; preload chunk0/kk0 frags; fill stage 2
    issue(0); issue(1);
    cp_wait<1>();
    __syncthreads();
    load_frags(sSm, sSm + STAGE_A, 0, 0);
    issue(2);

    for (int kt = 0; kt < KT; kt++) {
        const uint32_t aB = sSm + (kt % 3) * STAGE;
        const uint32_t bB = aB + STAGE_A;
        // kk = 0..2: load next frags (dual buffer) then MMA current
#pragma unroll
        for (int kk = 0; kk < 3; kk++) {
            load_frags(aB, bB, kk + 1, (kk & 1) ^ 1);
            do_mma(kk & 1);
        }
        // publish stage kt+1 CTA-wide + license rewrite of stage kt
        if (kt + 1 < KT) cp_wait<1>(); else cp_wait<0>();
        __syncthreads();
        // kk = 3: prefetch next chunk's kk0 frags + refill smem, both in MMA shadow
        if (kt + 1 < KT) {
            const uint32_t aB2 = sSm + ((kt + 1) % 3) * STAGE;
            load_frags(aB2, aB2 + STAGE_A, 0, 0);
        }
        if (kt + 3 < KT) issue(kt + 3);
        do_mma(1);
    }

    // -------- epilogue: smem patch -> gates -> c,h (coalesced, MUFU-light) --------
    __syncthreads();                       // everyone done with stage smem
    float* patch = (float*)smem;           // [128][136] floats
#pragma unroll
    for (int mi = 0; mi < 2; mi++)
#pragma unroll
        for (int ni = 0; ni < 8; ni++) {
            int r = wm + mi * 16 + (lane >> 2);
            int c = wn + ni * 8 + (lane & 3) * 2;
            *(float2*)(patch + r * B_PITCH + c)       = make_float2(acc[mi][ni][0], acc[mi][ni][1]);
            *(float2*)(patch + (r + 8) * B_PITCH + c) = make_float2(acc[mi][ni][2], acc[mi][ni][3]);
        }
    __syncthreads();

    const int jbase = nblk >> 2;           // 32 hidden units per CTA n-tile
#pragma unroll 4
    for (int it = 0; it < 16; it++) {
        int idx = it * 256 + tid;
        int row = idx >> 5;
        int u = idx & 31;
        float4 z = *(float4*)(patch + row * B_PITCH + u * 4);
        float4 bb = *(const float4*)(biasp + ((jbase + u) << 2));
        float ig = sigm_t(z.x + bb.x);
        float fg = sigm_t(z.y + bb.y);
        float gg = tanh_ap(z.z + bb.z);
        float og = sigm_t(z.w + bb.w);
        size_t off = (size_t)(mblk + row) * 1024 + jbase + u;
        float cn = fg * cst[off] + ig * gg;
        cst[off] = cn;
        hout[off] = __float2half(og * tanh_ap(cn));
    }
}

// ---------------- dense sigmoid head ----------------
__global__ void head_kernel(const float* __restrict__ Wd, const float* __restrict__ bd,
                            float* __restrict__ out) {
    int b = blockIdx.x;
    const __half* h = g_h2[1] + (size_t)b * 1024;   // t=127 -> cur buffer = 1
    float s = 0.f;
    for (int j = threadIdx.x; j < 1024; j += 128)
        s += __half2float(h[j]) * Wd[j];
#pragma unroll
    for (int o = 16; o; o >>= 1) s += __shfl_xor_sync(0xffffffffu, s, o);
    __shared__ float ws[4];
    if ((threadIdx.x & 31) == 0) ws[threadIdx.x >> 5] = s;
    __syncthreads();
    if (threadIdx.x == 0) {
        float t = ws[0] + ws[1] + ws[2] + ws[3] + bd[0];
        out[b] = 1.f / (1.f + __expf(-t));
    }
}

// ---------------- launch ----------------
extern "C" void kernel_launch(void* const* d_in, const int* in_sizes, int n_in,
                              void* d_out, int out_size) {
    (void)in_sizes; (void)n_in; (void)out_size;
    const float* x  = (const float*)d_in[0];
    const float* W1 = (const float*)d_in[1];
    const float* U1 = (const float*)d_in[2];
    const float* b1 = (const float*)d_in[3];
    const float* W2 = (const float*)d_in[4];
    const float* U2 = (const float*)d_in[5];
    const float* b2 = (const float*)d_in[6];
    const float* Wd = (const float*)d_in[7];
    const float* bd = (const float*)d_in[8];
    float* out = (float*)d_out;

    cudaFuncSetAttribute(lstm_pair, cudaFuncAttributeMaxDynamicSharedMemorySize, SMEM_TOTAL);

    pack_u1<<<(1088 * 1024 + 255) / 256, 256>>>(W1, U1);       // 1
    pack_u2<<<(2048 * 1024 + 255) / 256, 256>>>(W2, U2);       // 2
    prep_misc<<<(BB * TT * 64 + 255) / 256, 256>>>(x, b1, b2); // 3

    // wavefront: layer0@t0 (light, bids 128-255) + layer1@t0-1 (heavy, bids 0-127)
    for (int t0 = 0; t0 <= 128; t0++) {                        // 4 = first lstm (ncu slot)
        lstm_pair<<<256, 256, SMEM_TOTAL>>>(t0, t0 - 1);
    }
    head_kernel<<<512, 128>>>(Wd, bd, out);
}